// round 1
// baseline (speedup 1.0000x reference)
#include <cuda_runtime.h>
#include <cstddef>

#define BB 4
#define LL 2048
#define HH 8
#define DD 64
#define SK 40
#define NT 40
#define BHN 32          // B*H
#define NSPLIT 16
#define CHUNK 128       // keys per split block
#define SCALE 0.125f    // 1/sqrt(64)

// ---------------- scratch (device globals; no allocation allowed) ----------------
__device__ int   g_is64;
__device__ float g_M[BHN * LL];                 // 256 KB
__device__ int   g_top[BHN * NT];
__device__ float g_pm[BHN * NSPLIT * NT];
__device__ float g_pl[BHN * NSPLIT * NT];
__device__ float g_po[BHN * NSPLIT * NT * DD];  // 5.24 MB

// ---------------- kernel A: detect index dtype (int64 vs int32) ----------------
__global__ void detect_idx_kernel(const long long* __restrict__ idx64) {
    int ok = 1;
    for (int i = threadIdx.x; i < 512; i += 32) {
        long long v = idx64[i];
        if (v < 0 || v >= LL) ok = 0;
    }
    unsigned m = __ballot_sync(0xffffffffu, ok);
    if (threadIdx.x == 0) g_is64 = (m == 0xffffffffu) ? 1 : 0;
}

// ---------------- kernel B: M[bh][l] = max_s(q.k_s) - sum_s(q.k_s)/L ----------------
// warp per (bh, l); float2 per lane over D=64; xor-reduce per sampled key.
__global__ void sample_m_kernel(const float* __restrict__ Q,
                                const float* __restrict__ K,
                                const void*  __restrict__ idxbuf) {
    int wid  = (blockIdx.x * blockDim.x + threadIdx.x) >> 5;
    int lane = threadIdx.x & 31;
    int l  = wid % LL;
    int bh = wid / LL;
    int b = bh >> 3, h = bh & 7;

    int ia = 0, ib = 0;
    if (g_is64) {
        const long long* p = (const long long*)idxbuf + (long long)l * SK;
        ia = (int)p[lane];
        if (lane < SK - 32) ib = (int)p[32 + lane];
    } else {
        const int* p = (const int*)idxbuf + l * SK;
        ia = p[lane];
        if (lane < SK - 32) ib = p[32 + lane];
    }

    const float2 q = *(const float2*)(Q + (((size_t)(b * LL + l) * HH + h) << 6) + (lane << 1));

    float mx = -1e30f, sm = 0.0f;
#pragma unroll
    for (int s = 0; s < SK; s++) {
        int id = (s < 32) ? __shfl_sync(0xffffffffu, ia, s)
                          : __shfl_sync(0xffffffffu, ib, s - 32);
        const float2 k = *(const float2*)(K + (((size_t)(b * LL + id) * HH + h) << 6) + (lane << 1));
        float v = q.x * k.x + q.y * k.y;
        v += __shfl_xor_sync(0xffffffffu, v, 16);
        v += __shfl_xor_sync(0xffffffffu, v, 8);
        v += __shfl_xor_sync(0xffffffffu, v, 4);
        v += __shfl_xor_sync(0xffffffffu, v, 2);
        v += __shfl_xor_sync(0xffffffffu, v, 1);
        mx = fmaxf(mx, v);
        sm += v;
    }
    if (lane == 0) g_M[bh * LL + l] = mx - sm * (1.0f / (float)LL);
}

// ---------------- kernel C: top-40 per (bh); tie -> lower index (lax.top_k) ----------------
__global__ void topk_kernel() {
    __shared__ float sM[LL];
    __shared__ float rv[256];
    __shared__ int   ri[256];
    int bh = blockIdx.x, t = threadIdx.x;
    for (int i = t; i < LL; i += 256) sM[i] = g_M[bh * LL + i];
    __syncthreads();

    for (int it = 0; it < NT; it++) {
        float bv = -3e38f; int bi = LL;
        for (int i = t; i < LL; i += 256) {
            float v = sM[i];
            if (v > bv || (v == bv && i < bi)) { bv = v; bi = i; }
        }
        rv[t] = bv; ri[t] = bi;
        __syncthreads();
        for (int o = 128; o > 0; o >>= 1) {
            if (t < o) {
                float v2 = rv[t + o]; int i2 = ri[t + o];
                if (v2 > rv[t] || (v2 == rv[t] && i2 < ri[t])) { rv[t] = v2; ri[t] = i2; }
            }
            __syncthreads();
        }
        if (t == 0) { g_top[bh * NT + it] = ri[0]; sM[ri[0]] = -3e38f; }
        __syncthreads();
    }
}

// ---------------- kernel D: split-K attention ----------------
// block = (bh, split). smem: Qs[40*64] | Kt[64][132] (transposed,padded) | Vs[128][64] | Ss[40][128]
__global__ void attn_kernel(const float* __restrict__ Q,
                            const float* __restrict__ K,
                            const float* __restrict__ V) {
    extern __shared__ float smem[];
    int bh = blockIdx.x / NSPLIT, split = blockIdx.x % NSPLIT;
    int b = bh >> 3, h = bh & 7;
    int t = threadIdx.x;

    float* Qs = smem;                  // 2560
    float* Kt = Qs + NT * DD;          // 64*132 = 8448
    float* Vs = Kt + 64 * 132;         // 8192
    float* Ss = Vs + CHUNK * DD;       // 5120

    // load Q_reduce rows per top-k index
    for (int i = t; i < NT * DD; i += 256) {
        int u = i >> 6, d = i & 63;
        int ql = g_top[bh * NT + u];
        Qs[i] = Q[(((size_t)(b * LL + ql) * HH + h) << 6) + d];
    }
    int key0 = split * CHUNK;
    // load K (transposed into Kt[d][j], pad 132) and V (natural)
    for (int i = t; i < CHUNK * DD; i += 256) {
        int j = i >> 6, d = i & 63;
        size_t gbase = ((size_t)(b * LL + key0 + j) * HH + h) << 6;
        Kt[d * 132 + j] = K[gbase + d];
        Vs[i]           = V[gbase + d];
    }
    __syncthreads();

    // ---- phase 1: scores Ss[u][j] = scale * q_u . k_j ----
    {
        int ublk = t >> 5;          // 0..7 -> 5 queries each
        int jg   = t & 31;          // float4 group over j
        float4 acc[5];
#pragma unroll
        for (int k = 0; k < 5; k++) acc[k] = make_float4(0.f, 0.f, 0.f, 0.f);
        const float4* Kt4 = (const float4*)Kt;   // row = 33 float4
#pragma unroll 8
        for (int d = 0; d < 64; d++) {
            float4 kv = Kt4[d * 33 + jg];
#pragma unroll
            for (int k = 0; k < 5; k++) {
                float qv = Qs[(ublk * 5 + k) * 64 + d];
                acc[k].x += qv * kv.x;
                acc[k].y += qv * kv.y;
                acc[k].z += qv * kv.z;
                acc[k].w += qv * kv.w;
            }
        }
#pragma unroll
        for (int k = 0; k < 5; k++) {
            int u = ublk * 5 + k;
            float4 sv = make_float4(acc[k].x * SCALE, acc[k].y * SCALE,
                                    acc[k].z * SCALE, acc[k].w * SCALE);
            *(float4*)(Ss + u * CHUNK + (jg << 2)) = sv;
        }
    }
    __syncthreads();

    // ---- phase 1.5: per-row partial softmax (m, l), exp in place ----
    {
        int w = t >> 5, lane = t & 31;
        for (int r = w * 5; r < w * 5 + 5; r++) {
            float v0 = Ss[r * CHUNK + lane];
            float v1 = Ss[r * CHUNK + lane + 32];
            float v2 = Ss[r * CHUNK + lane + 64];
            float v3 = Ss[r * CHUNK + lane + 96];
            float m = fmaxf(fmaxf(v0, v1), fmaxf(v2, v3));
#pragma unroll
            for (int o = 16; o; o >>= 1) m = fmaxf(m, __shfl_xor_sync(0xffffffffu, m, o));
            float e0 = __expf(v0 - m), e1 = __expf(v1 - m);
            float e2 = __expf(v2 - m), e3 = __expf(v3 - m);
            Ss[r * CHUNK + lane]      = e0;
            Ss[r * CHUNK + lane + 32] = e1;
            Ss[r * CHUNK + lane + 64] = e2;
            Ss[r * CHUNK + lane + 96] = e3;
            float s = e0 + e1 + e2 + e3;
#pragma unroll
            for (int o = 16; o; o >>= 1) s += __shfl_xor_sync(0xffffffffu, s, o);
            if (lane == 0) {
                g_pm[(bh * NSPLIT + split) * NT + r] = m;
                g_pl[(bh * NSPLIT + split) * NT + r] = s;
            }
        }
    }
    __syncthreads();

    // ---- phase 2: O_partial = P @ V (j split in halves across threads) ----
    {
        int ublk = t >> 5;           // 0..7
        int d4   = t & 15;           // float4 group over d
        int jh   = (t >> 4) & 1;     // which 64-key half
        float4 acc[5];
#pragma unroll
        for (int k = 0; k < 5; k++) acc[k] = make_float4(0.f, 0.f, 0.f, 0.f);
        const float4* Vs4 = (const float4*)Vs;   // row = 16 float4
        int j0 = jh * 64;
#pragma unroll 4
        for (int jj = 0; jj < 64; jj++) {
            int j = j0 + jj;
            float4 vv = Vs4[j * 16 + d4];
#pragma unroll
            for (int k = 0; k < 5; k++) {
                float p = Ss[(ublk * 5 + k) * CHUNK + j];
                acc[k].x += p * vv.x;
                acc[k].y += p * vv.y;
                acc[k].z += p * vv.z;
                acc[k].w += p * vv.w;
            }
        }
        float* Opart = Kt;  // reuse (needs 2*2560 <= 8448)
#pragma unroll
        for (int k = 0; k < 5; k++) {
            int u = ublk * 5 + k;
            *(float4*)(Opart + (jh * NT + u) * 64 + (d4 << 2)) = acc[k];
        }
    }
    __syncthreads();

    for (int i = t; i < NT * DD; i += 256) {
        float v = Kt[i] + Kt[NT * DD + i];
        g_po[(size_t)(bh * NSPLIT + split) * NT * DD + i] = v;
    }
}

// ---------------- kernel F: combine splits + normalize + write out ----------------
__global__ void combine_kernel(float* __restrict__ out) {
    __shared__ float smx[NT], slx[NT];
    int bh = blockIdx.x, t = threadIdx.x;
    int b = bh >> 3, h = bh & 7;
    if (t < NT) {
        float m = -3e38f;
        for (int s = 0; s < NSPLIT; s++)
            m = fmaxf(m, g_pm[(bh * NSPLIT + s) * NT + t]);
        float Ls = 0.f;
        for (int s = 0; s < NSPLIT; s++)
            Ls += g_pl[(bh * NSPLIT + s) * NT + t] * __expf(g_pm[(bh * NSPLIT + s) * NT + t] - m);
        smx[t] = m; slx[t] = Ls;
    }
    __syncthreads();
    for (int i = t; i < NT * DD; i += 256) {
        int u = i >> 6, d = i & 63;
        float acc = 0.f;
        for (int s = 0; s < NSPLIT; s++) {
            float w = __expf(g_pm[(bh * NSPLIT + s) * NT + u] - smx[u]);
            acc += w * g_po[(size_t)(bh * NSPLIT + s) * NT * DD + i];
        }
        out[(((size_t)(b * NT + u) * HH + h) << 6) + d] = acc / slx[u];
    }
}

// ---------------- launcher ----------------
extern "C" void kernel_launch(void* const* d_in, const int* in_sizes, int n_in,
                              void* d_out, int out_size) {
    const float* Q   = (const float*)d_in[0];
    const float* K   = (const float*)d_in[1];
    const float* V   = (const float*)d_in[2];
    const void*  idx = d_in[3];

    detect_idx_kernel<<<1, 32>>>((const long long*)idx);
    sample_m_kernel<<<(BHN * LL) / 8, 256>>>(Q, K, idx);
    topk_kernel<<<BHN, 256>>>();

    size_t smemD = (size_t)(NT * DD + 64 * 132 + CHUNK * DD + NT * CHUNK) * sizeof(float); // 97280 B
    cudaFuncSetAttribute(attn_kernel, cudaFuncAttributeMaxDynamicSharedMemorySize, (int)smemD);
    attn_kernel<<<BHN * NSPLIT, 256, smemD>>>(Q, K, V);

    combine_kernel<<<BHN, 256>>>((float*)d_out);
}